// round 9
// baseline (speedup 1.0000x reference)
#include <cuda_runtime.h>
#include <math.h>
#include <stdint.h>

// ---------------- problem constants ----------------
#define NROWS 8192
#define IN_F  512
#define RFF   2048
#define OUT_F 1000
#define KBIG  (3*IN_F)
#define INV_RFF_SCALAR (1.0f/32.0f)
#define MFF   25.0f

// ---------------- tiling ----------------
#define BM 128
#define BN 128
#define BK 32
#define LDSS 36
#define A_FLOATS (128*LDSS)
#define STAGE_FLOATS (2*128*LDSS)
#define STAGE_BYTES (STAGE_FLOATS*4)   // 36864
#define NSTAGE 4
#define NTH 256
#define GRID_P 148                     // persistent: 1 CTA/SM (occupancy-1, 255 regs)

// ---------------- device scratch ----------------
__device__ float g_Phi[NROWS*RFF];
__device__ float g_Phi2[NROWS*RFF];
__device__ float g_Abig[NROWS*KBIG];
__device__ float g_Bbig[RFF*KBIG];
__device__ float g_diag_part[16*NROWS];
__device__ int   g_ctr[4];

// ---------------- helpers ----------------
__device__ __forceinline__ uint32_t smem_u32(const void* p) {
    uint32_t r;
    asm("{ .reg .u64 t; cvta.to.shared.u64 t, %1; cvt.u32.u64 %0, t; }" : "=r"(r) : "l"(p));
    return r;
}
__device__ __forceinline__ float to_tf32(float x) {
    float r; asm("cvt.rna.tf32.f32 %0, %1;" : "=f"(r) : "f"(x)); return r;
}
__device__ __forceinline__ void cp16(uint32_t d, const void* s) {
    asm volatile("cp.async.cg.shared.global [%0], [%1], 16;" :: "r"(d), "l"(s));
}
__device__ __forceinline__ void cp16z(uint32_t d, const void* s, uint32_t sz) {
    asm volatile("cp.async.cg.shared.global [%0], [%1], 16, %2;" :: "r"(d), "l"(s), "r"(sz));
}
__device__ __forceinline__ void cp_commit() { asm volatile("cp.async.commit_group;"); }
template <int N> __device__ __forceinline__ void cp_wait() {
    asm volatile("cp.async.wait_group %0;" :: "n"(N));
}
__device__ __forceinline__ void ldsm_x4(uint32_t* r, uint32_t a) {
    asm volatile("ldmatrix.sync.aligned.m8n8.x4.shared.b16 {%0,%1,%2,%3}, [%4];"
        : "=r"(r[0]), "=r"(r[1]), "=r"(r[2]), "=r"(r[3]) : "r"(a));
}
__device__ __forceinline__ void ldsm_x2(uint32_t* r, uint32_t a) {
    asm volatile("ldmatrix.sync.aligned.m8n8.x2.shared.b16 {%0,%1}, [%2];"
        : "=r"(r[0]), "=r"(r[1]) : "r"(a));
}
__device__ __forceinline__ void mma_tf32(float* c, const uint32_t* a, const uint32_t* b) {
    asm volatile(
        "mma.sync.aligned.m16n8k8.row.col.f32.tf32.tf32.f32 "
        "{%0,%1,%2,%3}, {%4,%5,%6,%7}, {%8,%9}, {%0,%1,%2,%3};"
        : "+f"(c[0]), "+f"(c[1]), "+f"(c[2]), "+f"(c[3])
        : "r"(a[0]), "r"(a[1]), "r"(a[2]), "r"(a[3]), "r"(b[0]), "r"(b[1]));
}

// ---------------- prep kernels ----------------
__global__ void split_D_k(const float* __restrict__ D, float* __restrict__ A) {
    int idx = blockIdx.x * blockDim.x + threadIdx.x;
    if (idx >= NROWS * IN_F) return;
    int r = idx >> 9, k = idx & (IN_F - 1);
    float x = D[idx], hi = to_tf32(x), lo = x - hi;
    float* p = A + (size_t)r * KBIG;
    p[k] = hi; p[IN_F + k] = to_tf32(lo); p[2 * IN_F + k] = hi;
}

__global__ void split_W_k(const float* __restrict__ W, float* __restrict__ Bb) {
    __shared__ float t[32][33];
    int nb = blockIdx.x * 32, kb = blockIdx.y * 32;
    int tx = threadIdx.x, ty0 = threadIdx.y;
    #pragma unroll
    for (int i = 0; i < 32; i += 8) {
        int ty = ty0 + i;
        t[ty][tx] = W[(size_t)(kb + ty) * RFF + nb + tx];
    }
    __syncthreads();
    #pragma unroll
    for (int i = 0; i < 32; i += 8) {
        int ty = ty0 + i;
        int n = nb + ty, k = kb + tx;
        float x = t[tx][ty], hi = to_tf32(x), lo = x - hi;
        float* p = Bb + (size_t)n * KBIG;
        p[k] = hi; p[IN_F + k] = hi; p[2 * IN_F + k] = to_tf32(lo);
    }
}

// ---------------- persistent mma.sync GEMM ----------------
// MODE 0: Phi = tf32(cos(acc+bias)/32), also Phi2 = 2*Phi
// MODE 1: diag partial = rowsum(acc*Phi); triangular K; A in {Phi2, Phi}; B = raw cov
// MODE 2: out = (acc+lb)*rsqrt(1+25*diag); B = raw logit_w zero-padded
template <int MODE>
__global__ void __launch_bounds__(NTH, 1)
gp_mma(const float* __restrict__ Ag, const float* __restrict__ Ag2,
       const float* __restrict__ Bg,
       const float* __restrict__ bias, float* __restrict__ outp,
       float* __restrict__ outp2,
       const float* __restrict__ phi, float* __restrict__ diagp,
       int* __restrict__ ctr, int nTiles, int K, int nIterFix)
{
    extern __shared__ float dyn[];
    __shared__ int s_tile;
    const int tid = threadIdx.x;
    const int wid = tid >> 5, lane = tid & 31;
    const int g = lane >> 2, t = lane & 3;
    const int warpM = wid >> 2, warpN = wid & 3;   // 2x4 warp grid, 64x32 warp tiles
    const uint32_t sbase = smem_u32(dyn);

    const uint32_t aLdOff = (uint32_t)(((warpM * 64 + ((lane >> 3) & 1) * 8 + (lane & 7)) * LDSS
                                        + ((lane >> 4) & 1) * 4) * 4);
    const uint32_t bLdOff = (uint32_t)(A_FLOATS * 4
                                        + ((warpN * 32 + (lane & 7)) * LDSS
                                        + ((lane >> 3) & 1) * 4) * 4);

    for (;;) {
        if (tid == 0) s_tile = atomicAdd(ctr, 1);
        __syncthreads();
        const int tile = s_tile;
        if (tile >= nTiles) break;

        int rowTile, colTile, cblk;
        if (MODE == 0)      { cblk = tile & 15; rowTile = (tile >> 4) * BM; }
        else if (MODE == 1) { cblk = 15 - (tile >> 6); rowTile = (tile & 63) * BM; }
        else                { cblk = tile & 7;  rowTile = (tile >> 3) * BM; }
        colTile = cblk * BN;
        const int nIter = (MODE == 1) ? ((colTile + BN) / BK) : nIterFix;  // >= 4

        float acc[4][4][4];
        #pragma unroll
        for (int mt = 0; mt < 4; mt++)
            #pragma unroll
            for (int nt = 0; nt < 4; nt++)
                #pragma unroll
                for (int r = 0; r < 4; r++) acc[mt][nt][r] = 0.0f;

        #define ISSUE(it, s) do {                                                  \
            const int _k0 = (it) * BK;                                             \
            const float* _as = (MODE == 1 && _k0 < colTile) ? Ag2 : Ag;            \
            _Pragma("unroll")                                                      \
            for (int j = 0; j < 4; j++) {                                          \
                int f = tid + NTH * j;                                             \
                int r = f >> 3, q = f & 7;                                         \
                uint32_t d = sbase + (uint32_t)(s) * STAGE_BYTES + (uint32_t)(r * LDSS + q * 4) * 4; \
                cp16(d, _as + (size_t)(rowTile + r) * K + _k0 + q * 4);            \
            }                                                                      \
            _Pragma("unroll")                                                      \
            for (int j = 0; j < 4; j++) {                                          \
                int f = tid + NTH * j;                                             \
                int r = f >> 3, q = f & 7;                                         \
                uint32_t d = sbase + (uint32_t)(s) * STAGE_BYTES + (uint32_t)(A_FLOATS + r * LDSS + q * 4) * 4; \
                if (MODE == 2) {                                                   \
                    int gn = colTile + r;                                          \
                    uint32_t sz = (gn < OUT_F) ? 16u : 0u;                         \
                    const float* src = Bg + (size_t)(sz ? gn : 0) * K + _k0 + q * 4; \
                    cp16z(d, src, sz);                                             \
                } else {                                                           \
                    cp16(d, Bg + (size_t)(colTile + r) * K + _k0 + q * 4);         \
                }                                                                  \
            }                                                                      \
            cp_commit();                                                           \
        } while (0)

        // prologue: 3 stages in flight (nIter >= 4)
        ISSUE(0, 0);
        ISSUE(1, 1);
        ISSUE(2, 2);

        int s = 0;
        for (int it = 0; it < nIter; ++it) {
            cp_wait<2>();             // group(it) complete (tail kept uniform w/ empty commits)
            __syncthreads();
            if (it + 3 < nIter) ISSUE(it + 3, (s + 3) & 3);
            else                cp_commit();   // empty group keeps wait<2> semantics exact

            const uint32_t aB = sbase + (uint32_t)s * STAGE_BYTES + aLdOff;
            const uint32_t bB = sbase + (uint32_t)s * STAGE_BYTES + bLdOff;

            uint32_t af[2][4][4], bf[2][4][2];
            #pragma unroll
            for (int mt = 0; mt < 4; mt++)
                ldsm_x4(af[0][mt], aB + (uint32_t)((mt * 16 * LDSS) * 4));
            #pragma unroll
            for (int nt = 0; nt < 4; nt++)
                ldsm_x2(bf[0][nt], bB + (uint32_t)((nt * 8 * LDSS) * 4));

            #pragma unroll
            for (int kk = 0; kk < 4; kk++) {
                const int cur = kk & 1, nxt = cur ^ 1;
                if (kk < 3) {
                    #pragma unroll
                    for (int mt = 0; mt < 4; mt++)
                        ldsm_x4(af[nxt][mt], aB + (uint32_t)((mt * 16 * LDSS + (kk + 1) * 8) * 4));
                    #pragma unroll
                    for (int nt = 0; nt < 4; nt++)
                        ldsm_x2(bf[nxt][nt], bB + (uint32_t)((nt * 8 * LDSS + (kk + 1) * 8) * 4));
                }
                #pragma unroll
                for (int mt = 0; mt < 4; mt++)
                    #pragma unroll
                    for (int nt = 0; nt < 4; nt++)
                        mma_tf32(acc[mt][nt], af[cur][mt], bf[cur][nt]);
            }
            s = (s + 1) & 3;
        }
        __syncthreads();

        // ---------------- epilogues ----------------
        if (MODE == 0) {
            #pragma unroll
            for (int mt = 0; mt < 4; mt++)
                #pragma unroll
                for (int h = 0; h < 2; h++) {
                    const int R = rowTile + warpM * 64 + mt * 16 + g + h * 8;
                    float* op  = outp  + (size_t)R * RFF;
                    float* op2 = outp2 + (size_t)R * RFF;
                    #pragma unroll
                    for (int nt = 0; nt < 4; nt++) {
                        const int C = colTile + warpN * 32 + nt * 8 + 2 * t;
                        float2 bb = *(const float2*)(bias + C);
                        float2 o, o2;
                        o.x = to_tf32(cosf(acc[mt][nt][h * 2 + 0] + bb.x) * INV_RFF_SCALAR);
                        o.y = to_tf32(cosf(acc[mt][nt][h * 2 + 1] + bb.y) * INV_RFF_SCALAR);
                        o2.x = 2.0f * o.x; o2.y = 2.0f * o.y;
                        *(float2*)(op + C) = o;
                        *(float2*)(op2 + C) = o2;
                    }
                }
        } else if (MODE == 1) {
            float* red = dyn;  // [128][4]
            #pragma unroll
            for (int mt = 0; mt < 4; mt++)
                #pragma unroll
                for (int h = 0; h < 2; h++) {
                    const int lr = warpM * 64 + mt * 16 + g + h * 8;
                    const float* pr = phi + (size_t)(rowTile + lr) * RFF;
                    float sum = 0.0f;
                    #pragma unroll
                    for (int nt = 0; nt < 4; nt++) {
                        const int C = colTile + warpN * 32 + nt * 8 + 2 * t;
                        float2 p = *(const float2*)(pr + C);
                        sum = fmaf(acc[mt][nt][h * 2 + 0], p.x, sum);
                        sum = fmaf(acc[mt][nt][h * 2 + 1], p.y, sum);
                    }
                    sum += __shfl_xor_sync(0xffffffffu, sum, 1);
                    sum += __shfl_xor_sync(0xffffffffu, sum, 2);
                    if (t == 0) red[lr * 4 + warpN] = sum;
                }
            __syncthreads();
            if (tid < 128) {
                float sum = red[tid * 4 + 0] + red[tid * 4 + 1] + red[tid * 4 + 2] + red[tid * 4 + 3];
                diagp[(size_t)cblk * NROWS + rowTile + tid] = sum;
            }
            __syncthreads();
        } else {
            float* scale = dyn;  // [128]
            if (tid < 128) {
                float dg = 0.0f;
                #pragma unroll
                for (int p = 0; p < 16; p++) dg += diagp[(size_t)p * NROWS + rowTile + tid];
                scale[tid] = rsqrtf(1.0f + MFF * dg);
            }
            __syncthreads();
            #pragma unroll
            for (int mt = 0; mt < 4; mt++)
                #pragma unroll
                for (int h = 0; h < 2; h++) {
                    const int lr = warpM * 64 + mt * 16 + g + h * 8;
                    const int R = rowTile + lr;
                    const float sc = scale[lr];
                    float* op = outp + (size_t)R * OUT_F;
                    #pragma unroll
                    for (int nt = 0; nt < 4; nt++) {
                        const int C = colTile + warpN * 32 + nt * 8 + 2 * t;
                        if (C < OUT_F) {
                            float2 bb = *(const float2*)(bias + C);
                            float2 o;
                            o.x = (acc[mt][nt][h * 2 + 0] + bb.x) * sc;
                            o.y = (acc[mt][nt][h * 2 + 1] + bb.y) * sc;
                            *(float2*)(op + C) = o;
                        }
                    }
                }
            __syncthreads();
        }
        #undef ISSUE
    }
}

// ---------------- host ----------------
extern "C" void kernel_launch(void* const* d_in, const int* in_sizes, int n_in,
                              void* d_out, int out_size)
{
    const float* D   = (const float*)d_in[0];
    const float* W   = (const float*)d_in[1];
    const float* b   = (const float*)d_in[2];
    const float* lw  = (const float*)d_in[3];
    const float* lb  = (const float*)d_in[4];
    const float* cov = (const float*)d_in[5];
    float* out = (float*)d_out;

    float *Phi, *Phi2, *Abig, *Bbig, *diagp;
    int* ctr;
    cudaGetSymbolAddress((void**)&Phi,   g_Phi);
    cudaGetSymbolAddress((void**)&Phi2,  g_Phi2);
    cudaGetSymbolAddress((void**)&Abig,  g_Abig);
    cudaGetSymbolAddress((void**)&Bbig,  g_Bbig);
    cudaGetSymbolAddress((void**)&diagp, g_diag_part);
    cudaGetSymbolAddress((void**)&ctr,   g_ctr);

    const int smem = NSTAGE * STAGE_BYTES;  // 147456 bytes
    cudaFuncSetAttribute(gp_mma<0>, cudaFuncAttributeMaxDynamicSharedMemorySize, smem);
    cudaFuncSetAttribute(gp_mma<1>, cudaFuncAttributeMaxDynamicSharedMemorySize, smem);
    cudaFuncSetAttribute(gp_mma<2>, cudaFuncAttributeMaxDynamicSharedMemorySize, smem);

    cudaMemsetAsync(ctr, 0, 4 * sizeof(int));

    split_D_k<<<(NROWS * IN_F + 255) / 256, 256>>>(D, Abig);
    split_W_k<<<dim3(RFF / 32, IN_F / 32), dim3(32, 8)>>>(W, Bbig);

    gp_mma<0><<<GRID_P, NTH, smem>>>(
        Abig, nullptr, Bbig, b, Phi, Phi2, nullptr, nullptr,
        ctr + 0, 1024, KBIG, KBIG / BK);
    gp_mma<1><<<GRID_P, NTH, smem>>>(
        Phi, Phi2, cov, nullptr, nullptr, nullptr, Phi, diagp,
        ctr + 1, 1024, RFF, 0);
    gp_mma<2><<<GRID_P, NTH, smem>>>(
        Phi, nullptr, lw, lb, out, nullptr, nullptr, diagp,
        ctr + 2, 512, RFF, RFF / BK);
}

// round 10
// speedup vs baseline: 1.3638x; 1.3638x over previous
#include <cuda_runtime.h>
#include <cuda_bf16.h>
#include <math.h>
#include <stdint.h>

// ---------------- problem constants ----------------
#define NROWS 8192
#define IN_F  512
#define RFF   2048
#define OUT_F 1000
#define KBIG  (3*IN_F)
#define INV_RFF_SCALAR (1.0f/32.0f)
#define MFF   25.0f

// ---------------- fp32/tf32 tiling (round-6 proven) ----------------
#define BM 128
#define BN 128
#define BK 32
#define LDSS 36
#define A_FLOATS (128*LDSS)
#define STAGE_FLOATS (2*128*LDSS)
#define STAGE_BYTES (STAGE_FLOATS*4)   // 36864
#define NSTAGE 3
#define NTH 256
#define GRID_P 296

// ---------------- bf16 tiling (GEMM2) ----------------
#define BKB 64
#define LDSH 72                        // halves per smem row (144 B)
#define AB_BYTES (128*LDSH*2)          // 18432
#define STAGE_BYTES_B (2*AB_BYTES)     // 36864 (same as fp32 stage)

// ---------------- device scratch ----------------
__device__ float g_Phi[NROWS*RFF];                 // tf32-exact fp32 (GEMM3 A, GEMM2 epi)
__device__ __nv_bfloat16 g_Phib [NROWS*RFF];       // bf16 Phi
__device__ __nv_bfloat16 g_Phib2[NROWS*RFF];       // 2*bf16 Phi (exact)
__device__ __nv_bfloat16 g_covb [RFF*RFF];         // bf16 cov
__device__ float g_Abig[NROWS*KBIG];
__device__ float g_Bbig[RFF*KBIG];
__device__ float g_diag_part[16*NROWS];
__device__ int   g_ctr[4];

// ---------------- helpers ----------------
__device__ __forceinline__ uint32_t smem_u32(const void* p) {
    uint32_t r;
    asm("{ .reg .u64 t; cvta.to.shared.u64 t, %1; cvt.u32.u64 %0, t; }" : "=r"(r) : "l"(p));
    return r;
}
__device__ __forceinline__ float to_tf32(float x) {
    float r; asm("cvt.rna.tf32.f32 %0, %1;" : "=f"(r) : "f"(x)); return r;
}
__device__ __forceinline__ void cp16(uint32_t d, const void* s) {
    asm volatile("cp.async.cg.shared.global [%0], [%1], 16;" :: "r"(d), "l"(s));
}
__device__ __forceinline__ void cp16z(uint32_t d, const void* s, uint32_t sz) {
    asm volatile("cp.async.cg.shared.global [%0], [%1], 16, %2;" :: "r"(d), "l"(s), "r"(sz));
}
__device__ __forceinline__ void cp_commit() { asm volatile("cp.async.commit_group;"); }
template <int N> __device__ __forceinline__ void cp_wait() {
    asm volatile("cp.async.wait_group %0;" :: "n"(N));
}
__device__ __forceinline__ void ldsm_x4(uint32_t* r, uint32_t a) {
    asm volatile("ldmatrix.sync.aligned.m8n8.x4.shared.b16 {%0,%1,%2,%3}, [%4];"
        : "=r"(r[0]), "=r"(r[1]), "=r"(r[2]), "=r"(r[3]) : "r"(a));
}
__device__ __forceinline__ void ldsm_x2(uint32_t* r, uint32_t a) {
    asm volatile("ldmatrix.sync.aligned.m8n8.x2.shared.b16 {%0,%1}, [%2];"
        : "=r"(r[0]), "=r"(r[1]) : "r"(a));
}
__device__ __forceinline__ void mma_tf32(float* c, const uint32_t* a, const uint32_t* b) {
    asm volatile(
        "mma.sync.aligned.m16n8k8.row.col.f32.tf32.tf32.f32 "
        "{%0,%1,%2,%3}, {%4,%5,%6,%7}, {%8,%9}, {%0,%1,%2,%3};"
        : "+f"(c[0]), "+f"(c[1]), "+f"(c[2]), "+f"(c[3])
        : "r"(a[0]), "r"(a[1]), "r"(a[2]), "r"(a[3]), "r"(b[0]), "r"(b[1]));
}
__device__ __forceinline__ void mma_bf16(float* c, const uint32_t* a, const uint32_t* b) {
    asm volatile(
        "mma.sync.aligned.m16n8k16.row.col.f32.bf16.bf16.f32 "
        "{%0,%1,%2,%3}, {%4,%5,%6,%7}, {%8,%9}, {%0,%1,%2,%3};"
        : "+f"(c[0]), "+f"(c[1]), "+f"(c[2]), "+f"(c[3])
        : "r"(a[0]), "r"(a[1]), "r"(a[2]), "r"(a[3]), "r"(b[0]), "r"(b[1]));
}

// ---------------- prep kernels ----------------
__global__ void split_D_k(const float* __restrict__ D, float* __restrict__ A) {
    int idx = blockIdx.x * blockDim.x + threadIdx.x;
    if (idx >= NROWS * IN_F) return;
    int r = idx >> 9, k = idx & (IN_F - 1);
    float x = D[idx], hi = to_tf32(x), lo = x - hi;
    float* p = A + (size_t)r * KBIG;
    p[k] = hi; p[IN_F + k] = to_tf32(lo); p[2 * IN_F + k] = hi;
}

__global__ void split_W_k(const float* __restrict__ W, float* __restrict__ Bb) {
    __shared__ float t[32][33];
    int nb = blockIdx.x * 32, kb = blockIdx.y * 32;
    int tx = threadIdx.x, ty0 = threadIdx.y;
    #pragma unroll
    for (int i = 0; i < 32; i += 8) {
        int ty = ty0 + i;
        t[ty][tx] = W[(size_t)(kb + ty) * RFF + nb + tx];
    }
    __syncthreads();
    #pragma unroll
    for (int i = 0; i < 32; i += 8) {
        int ty = ty0 + i;
        int n = nb + ty, k = kb + tx;
        float x = t[tx][ty], hi = to_tf32(x), lo = x - hi;
        float* p = Bb + (size_t)n * KBIG;
        p[k] = hi; p[IN_F + k] = hi; p[2 * IN_F + k] = to_tf32(lo);
    }
}

__global__ void cvt_covb(const float* __restrict__ c, __nv_bfloat16* __restrict__ o) {
    int idx = (blockIdx.x * blockDim.x + threadIdx.x) * 4;
    if (idx >= RFF * RFF) return;
    float4 v = *(const float4*)(c + idx);
    __nv_bfloat162 a, b;
    a.x = __float2bfloat16(v.x); a.y = __float2bfloat16(v.y);
    b.x = __float2bfloat16(v.z); b.y = __float2bfloat16(v.w);
    *(__nv_bfloat162*)(o + idx) = a;
    *(__nv_bfloat162*)(o + idx + 2) = b;
}

// ---------------- tf32 persistent GEMM (GEMM1 / GEMM3) ----------------
// MODE 0: Phi = tf32(cos(acc+bias)/32); also Phib = bf16(Phi), Phib2 = 2*Phib
// MODE 2: out = (acc+lb)*rsqrt(1+25*diag); B = raw logit_w zero-padded
template <int MODE>
__global__ void __launch_bounds__(NTH, 2)
gp_mma(const float* __restrict__ Ag, const float* __restrict__ Bg,
       const float* __restrict__ bias, float* __restrict__ outp,
       __nv_bfloat16* __restrict__ outpb, __nv_bfloat16* __restrict__ outpb2,
       float* __restrict__ diagp,
       int* __restrict__ ctr, int nTiles, int K, int nIter)
{
    extern __shared__ float dyn[];
    __shared__ int s_tile;
    const int tid = threadIdx.x;
    const int wid = tid >> 5, lane = tid & 31;
    const int g = lane >> 2, t = lane & 3;
    const int warpM = wid >> 2, warpN = wid & 3;   // 2x4 warp grid, 64x32 warp tiles
    const uint32_t sbase = smem_u32(dyn);

    const uint32_t aLdOff = (uint32_t)(((warpM * 64 + ((lane >> 3) & 1) * 8 + (lane & 7)) * LDSS
                                        + ((lane >> 4) & 1) * 4) * 4);
    const uint32_t bLdOff = (uint32_t)(A_FLOATS * 4
                                        + ((warpN * 32 + (lane & 7)) * LDSS
                                        + ((lane >> 3) & 1) * 4) * 4);

    for (;;) {
        if (tid == 0) s_tile = atomicAdd(ctr, 1);
        __syncthreads();
        const int tile = s_tile;
        if (tile >= nTiles) break;

        int rowTile, colTile;
        if (MODE == 0) { colTile = (tile & 15) * BN; rowTile = (tile >> 4) * BM; }
        else           { colTile = (tile & 7) * BN;  rowTile = (tile >> 3) * BM; }

        float acc[4][4][4];
        #pragma unroll
        for (int mt = 0; mt < 4; mt++)
            #pragma unroll
            for (int nt = 0; nt < 4; nt++)
                #pragma unroll
                for (int r = 0; r < 4; r++) acc[mt][nt][r] = 0.0f;

        #define ISSUE(it, s) do {                                                  \
            const int _k0 = (it) * BK;                                             \
            _Pragma("unroll")                                                      \
            for (int j = 0; j < 4; j++) {                                          \
                int f = tid + NTH * j;                                             \
                int r = f >> 3, q = f & 7;                                         \
                uint32_t d = sbase + (uint32_t)(s) * STAGE_BYTES + (uint32_t)(r * LDSS + q * 4) * 4; \
                cp16(d, Ag + (size_t)(rowTile + r) * K + _k0 + q * 4);             \
            }                                                                      \
            _Pragma("unroll")                                                      \
            for (int j = 0; j < 4; j++) {                                          \
                int f = tid + NTH * j;                                             \
                int r = f >> 3, q = f & 7;                                         \
                uint32_t d = sbase + (uint32_t)(s) * STAGE_BYTES + (uint32_t)(A_FLOATS + r * LDSS + q * 4) * 4; \
                if (MODE == 2) {                                                   \
                    int gn = colTile + r;                                          \
                    uint32_t sz = (gn < OUT_F) ? 16u : 0u;                         \
                    const float* src = Bg + (size_t)(sz ? gn : 0) * K + _k0 + q * 4; \
                    cp16z(d, src, sz);                                             \
                } else {                                                           \
                    cp16(d, Bg + (size_t)(colTile + r) * K + _k0 + q * 4);         \
                }                                                                  \
            }                                                                      \
            cp_commit();                                                           \
        } while (0)

        ISSUE(0, 0);
        ISSUE(1, 1);

        int s = 0;
        for (int it = 0; it < nIter; ++it) {
            if (it + 1 < nIter) cp_wait<1>(); else cp_wait<0>();
            __syncthreads();
            if (it + 2 < nIter) ISSUE(it + 2, (s + 2) % NSTAGE);

            const uint32_t aB = sbase + (uint32_t)s * STAGE_BYTES + aLdOff;
            const uint32_t bB = sbase + (uint32_t)s * STAGE_BYTES + bLdOff;
            #pragma unroll
            for (int kk = 0; kk < 4; kk++) {
                uint32_t af[4][4], bf[4][2];
                #pragma unroll
                for (int mt = 0; mt < 4; mt++)
                    ldsm_x4(af[mt], aB + (uint32_t)((mt * 16 * LDSS + kk * 8) * 4));
                #pragma unroll
                for (int nt = 0; nt < 4; nt++)
                    ldsm_x2(bf[nt], bB + (uint32_t)((nt * 8 * LDSS + kk * 8) * 4));
                #pragma unroll
                for (int mt = 0; mt < 4; mt++)
                    #pragma unroll
                    for (int nt = 0; nt < 4; nt++)
                        mma_tf32(acc[mt][nt], af[mt], bf[nt]);
            }
            s = (s + 1 == NSTAGE) ? 0 : s + 1;
        }
        __syncthreads();

        // ---------------- epilogues ----------------
        if (MODE == 0) {
            #pragma unroll
            for (int mt = 0; mt < 4; mt++)
                #pragma unroll
                for (int h = 0; h < 2; h++) {
                    const int R = rowTile + warpM * 64 + mt * 16 + g + h * 8;
                    float* op = outp + (size_t)R * RFF;
                    __nv_bfloat16* opb  = outpb  + (size_t)R * RFF;
                    __nv_bfloat16* opb2 = outpb2 + (size_t)R * RFF;
                    #pragma unroll
                    for (int nt = 0; nt < 4; nt++) {
                        const int C = colTile + warpN * 32 + nt * 8 + 2 * t;
                        float2 bb = *(const float2*)(bias + C);
                        float2 o;
                        o.x = to_tf32(cosf(acc[mt][nt][h * 2 + 0] + bb.x) * INV_RFF_SCALAR);
                        o.y = to_tf32(cosf(acc[mt][nt][h * 2 + 1] + bb.y) * INV_RFF_SCALAR);
                        *(float2*)(op + C) = o;
                        __nv_bfloat162 hb, hb2;
                        hb.x  = __float2bfloat16(o.x);       hb.y  = __float2bfloat16(o.y);
                        hb2.x = __float2bfloat16(2.0f*o.x);  hb2.y = __float2bfloat16(2.0f*o.y);
                        *(__nv_bfloat162*)(opb + C) = hb;
                        *(__nv_bfloat162*)(opb2 + C) = hb2;
                    }
                }
        } else {
            float* scale = dyn;  // [128]
            if (tid < 128) {
                float dg = 0.0f;
                #pragma unroll
                for (int p = 0; p < 16; p++) dg += diagp[(size_t)p * NROWS + rowTile + tid];
                scale[tid] = rsqrtf(1.0f + MFF * dg);
            }
            __syncthreads();
            #pragma unroll
            for (int mt = 0; mt < 4; mt++)
                #pragma unroll
                for (int h = 0; h < 2; h++) {
                    const int lr = warpM * 64 + mt * 16 + g + h * 8;
                    const int R = rowTile + lr;
                    const float sc = scale[lr];
                    float* op = outp + (size_t)R * OUT_F;
                    #pragma unroll
                    for (int nt = 0; nt < 4; nt++) {
                        const int C = colTile + warpN * 32 + nt * 8 + 2 * t;
                        if (C < OUT_F) {
                            float2 bb = *(const float2*)(bias + C);
                            float2 o;
                            o.x = (acc[mt][nt][h * 2 + 0] + bb.x) * sc;
                            o.y = (acc[mt][nt][h * 2 + 1] + bb.y) * sc;
                            *(float2*)(op + C) = o;
                        }
                    }
                }
            __syncthreads();
        }
        #undef ISSUE
    }
}

// ---------------- bf16 persistent GEMM2 (triangular diag) ----------------
__global__ void __launch_bounds__(NTH, 2)
gp_bf(const __nv_bfloat16* __restrict__ Phib, const __nv_bfloat16* __restrict__ Phib2,
      const __nv_bfloat16* __restrict__ covb,
      const float* __restrict__ phi, float* __restrict__ diagp,
      int* __restrict__ ctr, int nTiles)
{
    extern __shared__ float dyn[];
    __shared__ int s_tile;
    const int tid = threadIdx.x;
    const int wid = tid >> 5, lane = tid & 31;
    const int g = lane >> 2, t = lane & 3;
    const int warpM = wid >> 2, warpN = wid & 3;   // 64x32 warp tiles
    const uint32_t sbase = smem_u32(dyn);

    // canonical m16n8k16 ldmatrix lane addressing (byte offsets within stage)
    const uint32_t aOff = (uint32_t)((((warpM * 64 + ((lane >> 3) & 1) * 8 + (lane & 7)) * LDSH)
                                      + ((lane >> 4) & 1) * 8) * 2);
    const uint32_t bOff = (uint32_t)(AB_BYTES
                                      + (((warpN * 32 + ((lane >> 4) & 1) * 8 + (lane & 7)) * LDSH
                                      + ((lane >> 3) & 1) * 8) * 2));

    for (;;) {
        if (tid == 0) s_tile = atomicAdd(ctr, 1);
        __syncthreads();
        const int tile = s_tile;
        if (tile >= nTiles) break;
        const int cblk = 15 - (tile >> 6);          // LPT: long col-blocks first
        const int rowTile = (tile & 63) * BM;
        const int colTile = cblk * BN;
        const int nIter = (colTile + BN) / BKB;     // 2..32

        float acc[4][4][4];
        #pragma unroll
        for (int mt = 0; mt < 4; mt++)
            #pragma unroll
            for (int nt = 0; nt < 4; nt++)
                #pragma unroll
                for (int r = 0; r < 4; r++) acc[mt][nt][r] = 0.0f;

        #define ISSUEB(it, s) do {                                                 \
            const int _k0 = (it) * BKB;                                            \
            const __nv_bfloat16* _as = (_k0 < colTile) ? Phib2 : Phib;             \
            _Pragma("unroll")                                                      \
            for (int j = 0; j < 4; j++) {                                          \
                int f = tid + NTH * j;                                             \
                int r = f >> 3, q = f & 7;                                         \
                uint32_t d = sbase + (uint32_t)(s) * STAGE_BYTES_B + (uint32_t)((r * LDSH + q * 8) * 2); \
                cp16(d, _as + (size_t)(rowTile + r) * RFF + _k0 + q * 8);          \
            }                                                                      \
            _Pragma("unroll")                                                      \
            for (int j = 0; j < 4; j++) {                                          \
                int f = tid + NTH * j;                                             \
                int r = f >> 3, q = f & 7;                                         \
                uint32_t d = sbase + (uint32_t)(s) * STAGE_BYTES_B + (uint32_t)(AB_BYTES + (r * LDSH + q * 8) * 2); \
                cp16(d, covb + (size_t)(colTile + r) * RFF + _k0 + q * 8);         \
            }                                                                      \
            cp_commit();                                                           \
        } while (0)

        ISSUEB(0, 0);
        ISSUEB(1, 1);

        int s = 0;
        for (int it = 0; it < nIter; ++it) {
            if (it + 1 < nIter) cp_wait<1>(); else cp_wait<0>();
            __syncthreads();
            if (it + 2 < nIter) ISSUEB(it + 2, (s + 2) % NSTAGE);

            const uint32_t aB = sbase + (uint32_t)s * STAGE_BYTES_B + aOff;
            const uint32_t bB = sbase + (uint32_t)s * STAGE_BYTES_B + bOff;
            #pragma unroll
            for (int kk = 0; kk < 4; kk++) {        // 4 x k16 = BKB
                uint32_t af[4][4], bf[4][2];
                #pragma unroll
                for (int mt = 0; mt < 4; mt++)
                    ldsm_x4(af[mt], aB + (uint32_t)((mt * 16 * LDSH + kk * 16) * 2));
                #pragma unroll
                for (int np = 0; np < 2; np++) {
                    uint32_t r4[4];
                    ldsm_x4(r4, bB + (uint32_t)((np * 16 * LDSH + kk * 16) * 2));
                    bf[2 * np][0] = r4[0]; bf[2 * np][1] = r4[1];
                    bf[2 * np + 1][0] = r4[2]; bf[2 * np + 1][1] = r4[3];
                }
                #pragma unroll
                for (int mt = 0; mt < 4; mt++)
                    #pragma unroll
                    for (int nt = 0; nt < 4; nt++)
                        mma_bf16(acc[mt][nt], af[mt], bf[nt]);
            }
            s = (s + 1 == NSTAGE) ? 0 : s + 1;
        }
        __syncthreads();

        // epilogue: rowsum(acc * Phi) -> diag partial for this col-block
        float* red = dyn;  // [128][4]
        #pragma unroll
        for (int mt = 0; mt < 4; mt++)
            #pragma unroll
            for (int h = 0; h < 2; h++) {
                const int lr = warpM * 64 + mt * 16 + g + h * 8;
                const float* pr = phi + (size_t)(rowTile + lr) * RFF;
                float sum = 0.0f;
                #pragma unroll
                for (int nt = 0; nt < 4; nt++) {
                    const int C = colTile + warpN * 32 + nt * 8 + 2 * t;
                    float2 p = *(const float2*)(pr + C);
                    sum = fmaf(acc[mt][nt][h * 2 + 0], p.x, sum);
                    sum = fmaf(acc[mt][nt][h * 2 + 1], p.y, sum);
                }
                sum += __shfl_xor_sync(0xffffffffu, sum, 1);
                sum += __shfl_xor_sync(0xffffffffu, sum, 2);
                if (t == 0) red[lr * 4 + warpN] = sum;
            }
        __syncthreads();
        if (tid < 128) {
            float sum = red[tid * 4 + 0] + red[tid * 4 + 1] + red[tid * 4 + 2] + red[tid * 4 + 3];
            diagp[(size_t)cblk * NROWS + rowTile + tid] = sum;
        }
        __syncthreads();
        #undef ISSUEB
    }
}

// ---------------- host ----------------
extern "C" void kernel_launch(void* const* d_in, const int* in_sizes, int n_in,
                              void* d_out, int out_size)
{
    const float* D   = (const float*)d_in[0];
    const float* W   = (const float*)d_in[1];
    const float* b   = (const float*)d_in[2];
    const float* lw  = (const float*)d_in[3];
    const float* lb  = (const float*)d_in[4];
    const float* cov = (const float*)d_in[5];
    float* out = (float*)d_out;

    float *Phi, *Abig, *Bbig, *diagp;
    __nv_bfloat16 *Phib, *Phib2, *covb;
    int* ctr;
    cudaGetSymbolAddress((void**)&Phi,   g_Phi);
    cudaGetSymbolAddress((void**)&Phib,  g_Phib);
    cudaGetSymbolAddress((void**)&Phib2, g_Phib2);
    cudaGetSymbolAddress((void**)&covb,  g_covb);
    cudaGetSymbolAddress((void**)&Abig,  g_Abig);
    cudaGetSymbolAddress((void**)&Bbig,  g_Bbig);
    cudaGetSymbolAddress((void**)&diagp, g_diag_part);
    cudaGetSymbolAddress((void**)&ctr,   g_ctr);

    const int smem = NSTAGE * STAGE_BYTES;  // 110592 bytes
    cudaFuncSetAttribute(gp_mma<0>, cudaFuncAttributeMaxDynamicSharedMemorySize, smem);
    cudaFuncSetAttribute(gp_mma<2>, cudaFuncAttributeMaxDynamicSharedMemorySize, smem);
    cudaFuncSetAttribute(gp_bf,     cudaFuncAttributeMaxDynamicSharedMemorySize, smem);

    cudaMemsetAsync(ctr, 0, 4 * sizeof(int));

    split_D_k<<<(NROWS * IN_F + 255) / 256, 256>>>(D, Abig);
    split_W_k<<<dim3(RFF / 32, IN_F / 32), dim3(32, 8)>>>(W, Bbig);
    cvt_covb<<<(RFF * RFF / 4 + 255) / 256, 256>>>(cov, covb);

    // GEMM1: split-tf32, K=1536, 1024 tiles; writes Phi + Phib + Phib2
    gp_mma<0><<<GRID_P, NTH, smem>>>(
        Abig, Bbig, b, Phi, Phib, Phib2, nullptr,
        ctr + 0, 1024, KBIG, KBIG / BK);
    // GEMM2: bf16 triangular diag partials, 1024 tiles LPT
    gp_bf<<<GRID_P, NTH, smem>>>(
        Phib, Phib2, covb, Phi, diagp, ctr + 1, 1024);
    // GEMM3: tf32, K=2048, raw lw zero-padded, 512 tiles
    gp_mma<2><<<GRID_P, NTH, smem>>>(
        Phi, lw, lb, out, nullptr, nullptr, diagp,
        ctr + 2, 512, RFF, RFF / BK);
}

// round 11
// speedup vs baseline: 1.7361x; 1.2730x over previous
#include <cuda_runtime.h>
#include <cuda_bf16.h>
#include <math.h>
#include <stdint.h>

// ---------------- problem constants ----------------
#define NROWS 8192
#define IN_F  512
#define RFF   2048
#define OUT_F 1000
#define KBIG  (3*IN_F)                 // 1536: [Dhi|Dlo|Dhi] x [Whi|Whi|Wlo] (bf16)
#define INV_RFF_SCALAR (1.0f/32.0f)
#define MFF   25.0f

// ---------------- tf32 tiling (GEMM3) ----------------
#define BM 128
#define BN 128
#define BK 32
#define LDSS 36
#define A_FLOATS (128*LDSS)
#define STAGE_FLOATS (2*128*LDSS)
#define STAGE_BYTES (STAGE_FLOATS*4)   // 36864
#define NSTAGE 3
#define NTH 256
#define GRID_P 296

// ---------------- bf16 tiling (GEMM1 / GEMM2) ----------------
#define BKB 64
#define LDSH 72                        // halves per smem row (144 B)
#define AB_BYTES (128*LDSH*2)          // 18432
#define STAGE_BYTES_B (2*AB_BYTES)     // 36864

// ---------------- device scratch ----------------
__device__ float g_Phi[NROWS*RFF];                 // tf32-exact fp32
__device__ __nv_bfloat16 g_Phib [NROWS*RFF];
__device__ __nv_bfloat16 g_Phib2[NROWS*RFF];
__device__ __nv_bfloat16 g_covb [RFF*RFF];
__device__ __nv_bfloat16 g_Abb[NROWS*KBIG];        // 24 MB bf16 split D
__device__ __nv_bfloat16 g_Bbb[RFF*KBIG];          // 6 MB bf16 split W^T
__device__ float g_diag_part[16*NROWS];
__device__ int   g_ctr[4];

// ---------------- helpers ----------------
__device__ __forceinline__ uint32_t smem_u32(const void* p) {
    uint32_t r;
    asm("{ .reg .u64 t; cvta.to.shared.u64 t, %1; cvt.u32.u64 %0, t; }" : "=r"(r) : "l"(p));
    return r;
}
__device__ __forceinline__ float to_tf32(float x) {
    float r; asm("cvt.rna.tf32.f32 %0, %1;" : "=f"(r) : "f"(x)); return r;
}
__device__ __forceinline__ void cp16(uint32_t d, const void* s) {
    asm volatile("cp.async.cg.shared.global [%0], [%1], 16;" :: "r"(d), "l"(s));
}
__device__ __forceinline__ void cp16z(uint32_t d, const void* s, uint32_t sz) {
    asm volatile("cp.async.cg.shared.global [%0], [%1], 16, %2;" :: "r"(d), "l"(s), "r"(sz));
}
__device__ __forceinline__ void cp_commit() { asm volatile("cp.async.commit_group;"); }
template <int N> __device__ __forceinline__ void cp_wait() {
    asm volatile("cp.async.wait_group %0;" :: "n"(N));
}
__device__ __forceinline__ void ldsm_x4(uint32_t* r, uint32_t a) {
    asm volatile("ldmatrix.sync.aligned.m8n8.x4.shared.b16 {%0,%1,%2,%3}, [%4];"
        : "=r"(r[0]), "=r"(r[1]), "=r"(r[2]), "=r"(r[3]) : "r"(a));
}
__device__ __forceinline__ void ldsm_x2(uint32_t* r, uint32_t a) {
    asm volatile("ldmatrix.sync.aligned.m8n8.x2.shared.b16 {%0,%1}, [%2];"
        : "=r"(r[0]), "=r"(r[1]) : "r"(a));
}
__device__ __forceinline__ void mma_tf32(float* c, const uint32_t* a, const uint32_t* b) {
    asm volatile(
        "mma.sync.aligned.m16n8k8.row.col.f32.tf32.tf32.f32 "
        "{%0,%1,%2,%3}, {%4,%5,%6,%7}, {%8,%9}, {%0,%1,%2,%3};"
        : "+f"(c[0]), "+f"(c[1]), "+f"(c[2]), "+f"(c[3])
        : "r"(a[0]), "r"(a[1]), "r"(a[2]), "r"(a[3]), "r"(b[0]), "r"(b[1]));
}
__device__ __forceinline__ void mma_bf16(float* c, const uint32_t* a, const uint32_t* b) {
    asm volatile(
        "mma.sync.aligned.m16n8k16.row.col.f32.bf16.bf16.f32 "
        "{%0,%1,%2,%3}, {%4,%5,%6,%7}, {%8,%9}, {%0,%1,%2,%3};"
        : "+f"(c[0]), "+f"(c[1]), "+f"(c[2]), "+f"(c[3])
        : "r"(a[0]), "r"(a[1]), "r"(a[2]), "r"(a[3]), "r"(b[0]), "r"(b[1]));
}

// ---------------- prep kernels ----------------
__global__ void split_D_b(const float* __restrict__ D, __nv_bfloat16* __restrict__ A) {
    int idx = blockIdx.x * blockDim.x + threadIdx.x;
    if (idx >= NROWS * IN_F) return;
    int r = idx >> 9, k = idx & (IN_F - 1);
    float x = D[idx];
    __nv_bfloat16 hi = __float2bfloat16(x);
    __nv_bfloat16 lo = __float2bfloat16(x - __bfloat162float(hi));
    __nv_bfloat16* p = A + (size_t)r * KBIG;
    p[k] = hi; p[IN_F + k] = lo; p[2 * IN_F + k] = hi;
}

__global__ void split_W_b(const float* __restrict__ W, __nv_bfloat16* __restrict__ Bb) {
    __shared__ float t[32][33];
    int nb = blockIdx.x * 32, kb = blockIdx.y * 32;
    int tx = threadIdx.x, ty0 = threadIdx.y;
    #pragma unroll
    for (int i = 0; i < 32; i += 8) {
        int ty = ty0 + i;
        t[ty][tx] = W[(size_t)(kb + ty) * RFF + nb + tx];
    }
    __syncthreads();
    #pragma unroll
    for (int i = 0; i < 32; i += 8) {
        int ty = ty0 + i;
        int n = nb + ty, k = kb + tx;
        float x = t[tx][ty];
        __nv_bfloat16 hi = __float2bfloat16(x);
        __nv_bfloat16 lo = __float2bfloat16(x - __bfloat162float(hi));
        __nv_bfloat16* p = Bb + (size_t)n * KBIG;
        p[k] = hi; p[IN_F + k] = hi; p[2 * IN_F + k] = lo;
    }
}

__global__ void cvt_covb(const float* __restrict__ c, __nv_bfloat16* __restrict__ o) {
    int idx = (blockIdx.x * blockDim.x + threadIdx.x) * 4;
    if (idx >= RFF * RFF) return;
    float4 v = *(const float4*)(c + idx);
    __nv_bfloat162 a, b;
    a.x = __float2bfloat16(v.x); a.y = __float2bfloat16(v.y);
    b.x = __float2bfloat16(v.z); b.y = __float2bfloat16(v.w);
    *(__nv_bfloat162*)(o + idx) = a;
    *(__nv_bfloat162*)(o + idx + 2) = b;
}

// ---------------- bf16 persistent GEMM (GEMM1 / GEMM2) ----------------
// MODE 0: Phi = tf32(cos(acc+bias)/32) + Phib + Phib2; A=g_Abb, B=g_Bbb, K=KBIG, 24 iters
// MODE 1: diag partial = rowsum(acc*Phi); triangular K; A in {Phib2, Phib}; B=covb
template <int MODE>
__global__ void __launch_bounds__(NTH, 2)
gp_bf(const __nv_bfloat16* __restrict__ Ag, const __nv_bfloat16* __restrict__ Ag2,
      const __nv_bfloat16* __restrict__ Bg,
      const float* __restrict__ bias, float* __restrict__ outp,
      __nv_bfloat16* __restrict__ outpb, __nv_bfloat16* __restrict__ outpb2,
      const float* __restrict__ phi, float* __restrict__ diagp,
      int* __restrict__ ctr, int nTiles, int K, int nIterFix)
{
    extern __shared__ float dyn[];
    __shared__ int s_tile;
    const int tid = threadIdx.x;
    const int wid = tid >> 5, lane = tid & 31;
    const int g = lane >> 2, t = lane & 3;
    const int warpM = wid >> 2, warpN = wid & 3;   // 2x4 warp grid, 64x32 warp tiles
    const uint32_t sbase = smem_u32(dyn);

    const uint32_t aOff = (uint32_t)((((warpM * 64 + ((lane >> 3) & 1) * 8 + (lane & 7)) * LDSH)
                                      + ((lane >> 4) & 1) * 8) * 2);
    const uint32_t bOff = (uint32_t)(AB_BYTES
                                      + (((warpN * 32 + ((lane >> 4) & 1) * 8 + (lane & 7)) * LDSH
                                      + ((lane >> 3) & 1) * 8) * 2));

    for (;;) {
        if (tid == 0) s_tile = atomicAdd(ctr, 1);
        __syncthreads();
        const int tile = s_tile;
        if (tile >= nTiles) break;

        int rowTile, colTile, cblk;
        if (MODE == 0) { cblk = tile & 15; rowTile = (tile >> 4) * BM; }
        else           { cblk = 15 - (tile >> 6); rowTile = (tile & 63) * BM; }
        colTile = cblk * BN;
        const int nIter = (MODE == 1) ? ((colTile + BN) / BKB) : nIterFix;

        float acc[4][4][4];
        #pragma unroll
        for (int mt = 0; mt < 4; mt++)
            #pragma unroll
            for (int nt = 0; nt < 4; nt++)
                #pragma unroll
                for (int r = 0; r < 4; r++) acc[mt][nt][r] = 0.0f;

        #define ISSUEB(it, s) do {                                                 \
            const int _k0 = (it) * BKB;                                            \
            const __nv_bfloat16* _as = (MODE == 1 && _k0 < colTile) ? Ag2 : Ag;    \
            _Pragma("unroll")                                                      \
            for (int j = 0; j < 4; j++) {                                          \
                int f = tid + NTH * j;                                             \
                int r = f >> 3, q = f & 7;                                         \
                uint32_t d = sbase + (uint32_t)(s) * STAGE_BYTES_B + (uint32_t)((r * LDSH + q * 8) * 2); \
                cp16(d, _as + (size_t)(rowTile + r) * K + _k0 + q * 8);            \
            }                                                                      \
            _Pragma("unroll")                                                      \
            for (int j = 0; j < 4; j++) {                                          \
                int f = tid + NTH * j;                                             \
                int r = f >> 3, q = f & 7;                                         \
                uint32_t d = sbase + (uint32_t)(s) * STAGE_BYTES_B + (uint32_t)(AB_BYTES + (r * LDSH + q * 8) * 2); \
                cp16(d, Bg + (size_t)(colTile + r) * K + _k0 + q * 8);             \
            }                                                                      \
            cp_commit();                                                           \
        } while (0)

        ISSUEB(0, 0);
        ISSUEB(1, 1);

        int s = 0;
        for (int it = 0; it < nIter; ++it) {
            if (it + 1 < nIter) cp_wait<1>(); else cp_wait<0>();
            __syncthreads();
            if (it + 2 < nIter) ISSUEB(it + 2, (s + 2) % NSTAGE);

            const uint32_t aB = sbase + (uint32_t)s * STAGE_BYTES_B + aOff;
            const uint32_t bB = sbase + (uint32_t)s * STAGE_BYTES_B + bOff;
            #pragma unroll
            for (int kk = 0; kk < 4; kk++) {        // 4 x k16 = BKB
                uint32_t af[4][4], bf[4][2];
                #pragma unroll
                for (int mt = 0; mt < 4; mt++)
                    ldsm_x4(af[mt], aB + (uint32_t)((mt * 16 * LDSH + kk * 16) * 2));
                #pragma unroll
                for (int np = 0; np < 2; np++) {
                    uint32_t r4[4];
                    ldsm_x4(r4, bB + (uint32_t)((np * 16 * LDSH + kk * 16) * 2));
                    bf[2 * np][0] = r4[0]; bf[2 * np][1] = r4[1];
                    bf[2 * np + 1][0] = r4[2]; bf[2 * np + 1][1] = r4[3];
                }
                #pragma unroll
                for (int mt = 0; mt < 4; mt++)
                    #pragma unroll
                    for (int nt = 0; nt < 4; nt++)
                        mma_bf16(acc[mt][nt], af[mt], bf[nt]);
            }
            s = (s + 1 == NSTAGE) ? 0 : s + 1;
        }
        __syncthreads();

        // ---------------- epilogues ----------------
        if (MODE == 0) {
            #pragma unroll
            for (int mt = 0; mt < 4; mt++)
                #pragma unroll
                for (int h = 0; h < 2; h++) {
                    const int R = rowTile + warpM * 64 + mt * 16 + g + h * 8;
                    float* op = outp + (size_t)R * RFF;
                    __nv_bfloat16* opb  = outpb  + (size_t)R * RFF;
                    __nv_bfloat16* opb2 = outpb2 + (size_t)R * RFF;
                    #pragma unroll
                    for (int nt = 0; nt < 4; nt++) {
                        const int C = colTile + warpN * 32 + nt * 8 + 2 * t;
                        float2 bb = *(const float2*)(bias + C);
                        float2 o;
                        o.x = to_tf32(cosf(acc[mt][nt][h * 2 + 0] + bb.x) * INV_RFF_SCALAR);
                        o.y = to_tf32(cosf(acc[mt][nt][h * 2 + 1] + bb.y) * INV_RFF_SCALAR);
                        *(float2*)(op + C) = o;
                        __nv_bfloat162 hb, hb2;
                        hb.x  = __float2bfloat16(o.x);        hb.y  = __float2bfloat16(o.y);
                        hb2.x = __float2bfloat16(2.0f * o.x); hb2.y = __float2bfloat16(2.0f * o.y);
                        *(__nv_bfloat162*)(opb + C) = hb;
                        *(__nv_bfloat162*)(opb2 + C) = hb2;
                    }
                }
        } else {
            float* red = dyn;  // [128][4]
            #pragma unroll
            for (int mt = 0; mt < 4; mt++)
                #pragma unroll
                for (int h = 0; h < 2; h++) {
                    const int lr = warpM * 64 + mt * 16 + g + h * 8;
                    const float* pr = phi + (size_t)(rowTile + lr) * RFF;
                    float sum = 0.0f;
                    #pragma unroll
                    for (int nt = 0; nt < 4; nt++) {
                        const int C = colTile + warpN * 32 + nt * 8 + 2 * t;
                        float2 p = *(const float2*)(pr + C);
                        sum = fmaf(acc[mt][nt][h * 2 + 0], p.x, sum);
                        sum = fmaf(acc[mt][nt][h * 2 + 1], p.y, sum);
                    }
                    sum += __shfl_xor_sync(0xffffffffu, sum, 1);
                    sum += __shfl_xor_sync(0xffffffffu, sum, 2);
                    if (t == 0) red[lr * 4 + warpN] = sum;
                }
            __syncthreads();
            if (tid < 128) {
                float sum = red[tid * 4 + 0] + red[tid * 4 + 1] + red[tid * 4 + 2] + red[tid * 4 + 3];
                diagp[(size_t)cblk * NROWS + rowTile + tid] = sum;
            }
            __syncthreads();
        }
        #undef ISSUEB
    }
}

// ---------------- tf32 persistent GEMM3 ----------------
__global__ void __launch_bounds__(NTH, 2)
gp_mma3(const float* __restrict__ Ag, const float* __restrict__ Bg,
        const float* __restrict__ bias, float* __restrict__ outp,
        const float* __restrict__ diagp,
        int* __restrict__ ctr, int nTiles, int K, int nIter)
{
    extern __shared__ float dyn[];
    __shared__ int s_tile;
    const int tid = threadIdx.x;
    const int wid = tid >> 5, lane = tid & 31;
    const int g = lane >> 2, t = lane & 3;
    const int warpM = wid >> 2, warpN = wid & 3;
    const uint32_t sbase = smem_u32(dyn);

    const uint32_t aLdOff = (uint32_t)(((warpM * 64 + ((lane >> 3) & 1) * 8 + (lane & 7)) * LDSS
                                        + ((lane >> 4) & 1) * 4) * 4);
    const uint32_t bLdOff = (uint32_t)(A_FLOATS * 4
                                        + ((warpN * 32 + (lane & 7)) * LDSS
                                        + ((lane >> 3) & 1) * 4) * 4);

    for (;;) {
        if (tid == 0) s_tile = atomicAdd(ctr, 1);
        __syncthreads();
        const int tile = s_tile;
        if (tile >= nTiles) break;

        const int colTile = (tile & 7) * BN;
        const int rowTile = (tile >> 3) * BM;

        float acc[4][4][4];
        #pragma unroll
        for (int mt = 0; mt < 4; mt++)
            #pragma unroll
            for (int nt = 0; nt < 4; nt++)
                #pragma unroll
                for (int r = 0; r < 4; r++) acc[mt][nt][r] = 0.0f;

        #define ISSUE3(it, s) do {                                                 \
            const int _k0 = (it) * BK;                                             \
            _Pragma("unroll")                                                      \
            for (int j = 0; j < 4; j++) {                                          \
                int f = tid + NTH * j;                                             \
                int r = f >> 3, q = f & 7;                                         \
                uint32_t d = sbase + (uint32_t)(s) * STAGE_BYTES + (uint32_t)(r * LDSS + q * 4) * 4; \
                cp16(d, Ag + (size_t)(rowTile + r) * K + _k0 + q * 4);             \
            }                                                                      \
            _Pragma("unroll")                                                      \
            for (int j = 0; j < 4; j++) {                                          \
                int f = tid + NTH * j;                                             \
                int r = f >> 3, q = f & 7;                                         \
                uint32_t d = sbase + (uint32_t)(s) * STAGE_BYTES + (uint32_t)(A_FLOATS + r * LDSS + q * 4) * 4; \
                int gn = colTile + r;                                              \
                uint32_t sz = (gn < OUT_F) ? 16u : 0u;                             \
                const float* src = Bg + (size_t)(sz ? gn : 0) * K + _k0 + q * 4;   \
                cp16z(d, src, sz);                                                 \
            }                                                                      \
            cp_commit();                                                           \
        } while (0)

        ISSUE3(0, 0);
        ISSUE3(1, 1);

        int s = 0;
        for (int it = 0; it < nIter; ++it) {
            if (it + 1 < nIter) cp_wait<1>(); else cp_wait<0>();
            __syncthreads();
            if (it + 2 < nIter) ISSUE3(it + 2, (s + 2) % NSTAGE);

            const uint32_t aB = sbase + (uint32_t)s * STAGE_BYTES + aLdOff;
            const uint32_t bB = sbase + (uint32_t)s * STAGE_BYTES + bLdOff;
            #pragma unroll
            for (int kk = 0; kk < 4; kk++) {
                uint32_t af[4][4], bf[4][2];
                #pragma unroll
                for (int mt = 0; mt < 4; mt++)
                    ldsm_x4(af[mt], aB + (uint32_t)((mt * 16 * LDSS + kk * 8) * 4));
                #pragma unroll
                for (int nt = 0; nt < 4; nt++)
                    ldsm_x2(bf[nt], bB + (uint32_t)((nt * 8 * LDSS + kk * 8) * 4));
                #pragma unroll
                for (int mt = 0; mt < 4; mt++)
                    #pragma unroll
                    for (int nt = 0; nt < 4; nt++)
                        mma_tf32(acc[mt][nt], af[mt], bf[nt]);
            }
            s = (s + 1 == NSTAGE) ? 0 : s + 1;
        }
        __syncthreads();

        float* scale = dyn;  // [128]
        if (tid < 128) {
            float dg = 0.0f;
            #pragma unroll
            for (int p = 0; p < 16; p++) dg += diagp[(size_t)p * NROWS + rowTile + tid];
            scale[tid] = rsqrtf(1.0f + MFF * dg);
        }
        __syncthreads();
        #pragma unroll
        for (int mt = 0; mt < 4; mt++)
            #pragma unroll
            for (int h = 0; h < 2; h++) {
                const int lr = warpM * 64 + mt * 16 + g + h * 8;
                const int R = rowTile + lr;
                const float sc = scale[lr];
                float* op = outp + (size_t)R * OUT_F;
                #pragma unroll
                for (int nt = 0; nt < 4; nt++) {
                    const int C = colTile + warpN * 32 + nt * 8 + 2 * t;
                    if (C < OUT_F) {
                        float2 bb = *(const float2*)(bias + C);
                        float2 o;
                        o.x = (acc[mt][nt][h * 2 + 0] + bb.x) * sc;
                        o.y = (acc[mt][nt][h * 2 + 1] + bb.y) * sc;
                        *(float2*)(op + C) = o;
                    }
                }
            }
        __syncthreads();
        #undef ISSUE3
    }
}

// ---------------- host ----------------
extern "C" void kernel_launch(void* const* d_in, const int* in_sizes, int n_in,
                              void* d_out, int out_size)
{
    const float* D   = (const float*)d_in[0];
    const float* W   = (const float*)d_in[1];
    const float* b   = (const float*)d_in[2];
    const float* lw  = (const float*)d_in[3];
    const float* lb  = (const float*)d_in[4];
    const float* cov = (const float*)d_in[5];
    float* out = (float*)d_out;

    float *Phi, *diagp;
    __nv_bfloat16 *Phib, *Phib2, *covb, *Abb, *Bbb;
    int* ctr;
    cudaGetSymbolAddress((void**)&Phi,   g_Phi);
    cudaGetSymbolAddress((void**)&Phib,  g_Phib);
    cudaGetSymbolAddress((void**)&Phib2, g_Phib2);
    cudaGetSymbolAddress((void**)&covb,  g_covb);
    cudaGetSymbolAddress((void**)&Abb,   g_Abb);
    cudaGetSymbolAddress((void**)&Bbb,   g_Bbb);
    cudaGetSymbolAddress((void**)&diagp, g_diag_part);
    cudaGetSymbolAddress((void**)&ctr,   g_ctr);

    const int smem = NSTAGE * STAGE_BYTES;  // 110592 bytes
    cudaFuncSetAttribute(gp_bf<0>, cudaFuncAttributeMaxDynamicSharedMemorySize, smem);
    cudaFuncSetAttribute(gp_bf<1>, cudaFuncAttributeMaxDynamicSharedMemorySize, smem);
    cudaFuncSetAttribute(gp_mma3,  cudaFuncAttributeMaxDynamicSharedMemorySize, smem);

    cudaMemsetAsync(ctr, 0, 4 * sizeof(int));

    split_D_b<<<(NROWS * IN_F + 255) / 256, 256>>>(D, Abb);
    split_W_b<<<dim3(RFF / 32, IN_F / 32), dim3(32, 8)>>>(W, Bbb);
    cvt_covb<<<(RFF * RFF / 4 + 255) / 256, 256>>>(cov, covb);

    // GEMM1: bf16 3-product split, K=1536, 1024 tiles; writes Phi + Phib + Phib2
    gp_bf<0><<<GRID_P, NTH, smem>>>(
        Abb, nullptr, Bbb, b, Phi, Phib, Phib2, nullptr, nullptr,
        ctr + 0, 1024, KBIG, KBIG / BKB);
    // GEMM2: bf16 triangular diag partials, 1024 tiles LPT
    gp_bf<1><<<GRID_P, NTH, smem>>>(
        Phib, Phib2, covb, nullptr, nullptr, nullptr, nullptr, Phi, diagp,
        ctr + 1, 1024, RFF, 0);
    // GEMM3: tf32, K=2048, raw lw zero-padded, 512 tiles
    gp_mma3<<<GRID_P, NTH, smem>>>(
        Phi, lw, lb, out, diagp, ctr + 2, 512, RFF, RFF / BK);
}

// round 12
// speedup vs baseline: 2.1302x; 1.2270x over previous
#include <cuda_runtime.h>
#include <cuda_fp16.h>
#include <math.h>
#include <stdint.h>

// ---------------- problem constants ----------------
#define NROWS 8192
#define IN_F  512
#define RFF   2048
#define OUT_F 1000
#define OUT_P 1024
#define KBIG  (3*IN_F)                 // 1536: [Dhi|Dlo|Dhi] x [Whi|Whi|Wlo] (fp16)
#define INV_RFF_SCALAR (1.0f/32.0f)
#define MFF   25.0f

// ---------------- fp16 tiling (all GEMMs) ----------------
#define BM 128
#define BN 128
#define BKB 64
#define LDSH 72                        // halves per smem row (144 B)
#define AB_BYTES (128*LDSH*2)          // 18432
#define STAGE_BYTES_B (2*AB_BYTES)     // 36864
#define NSTAGE 3
#define NTH 256
#define GRID_P 296

// ---------------- device scratch ----------------
__device__ float  g_Phi[NROWS*RFF];                // fp32 (fp16-exact values), GEMM2 epilogue
__device__ __half g_Phih [NROWS*RFF];              // fp16 Phi (exact)
__device__ __half g_Phih2[NROWS*RFF];              // 2*Phi (exact)
__device__ __half g_covh [RFF*RFF];                // fp16 cov
__device__ __half g_lwh  [OUT_P*RFF];              // fp16 logit_w, zero-padded rows >= 1000
__device__ __half g_Abh[NROWS*KBIG];               // fp16 split D
__device__ __half g_Bbh[RFF*KBIG];                 // fp16 split W^T
__device__ float  g_diag_part[16*NROWS];
__device__ int    g_ctr[4];

// ---------------- helpers ----------------
__device__ __forceinline__ uint32_t smem_u32(const void* p) {
    uint32_t r;
    asm("{ .reg .u64 t; cvta.to.shared.u64 t, %1; cvt.u32.u64 %0, t; }" : "=r"(r) : "l"(p));
    return r;
}
__device__ __forceinline__ void cp16(uint32_t d, const void* s) {
    asm volatile("cp.async.cg.shared.global [%0], [%1], 16;" :: "r"(d), "l"(s));
}
__device__ __forceinline__ void cp_commit() { asm volatile("cp.async.commit_group;"); }
template <int N> __device__ __forceinline__ void cp_wait() {
    asm volatile("cp.async.wait_group %0;" :: "n"(N));
}
__device__ __forceinline__ void ldsm_x4(uint32_t* r, uint32_t a) {
    asm volatile("ldmatrix.sync.aligned.m8n8.x4.shared.b16 {%0,%1,%2,%3}, [%4];"
        : "=r"(r[0]), "=r"(r[1]), "=r"(r[2]), "=r"(r[3]) : "r"(a));
}
__device__ __forceinline__ void mma_f16(float* c, const uint32_t* a, const uint32_t* b) {
    asm volatile(
        "mma.sync.aligned.m16n8k16.row.col.f32.f16.f16.f32 "
        "{%0,%1,%2,%3}, {%4,%5,%6,%7}, {%8,%9}, {%0,%1,%2,%3};"
        : "+f"(c[0]), "+f"(c[1]), "+f"(c[2]), "+f"(c[3])
        : "r"(a[0]), "r"(a[1]), "r"(a[2]), "r"(a[3]), "r"(b[0]), "r"(b[1]));
}

// ---------------- prep kernels ----------------
__global__ void split_D_h(const float* __restrict__ D, __half* __restrict__ A) {
    int idx = blockIdx.x * blockDim.x + threadIdx.x;
    if (idx >= NROWS * IN_F) return;
    int r = idx >> 9, k = idx & (IN_F - 1);
    float x = D[idx];
    __half hi = __float2half(x);
    __half lo = __float2half(x - __half2float(hi));
    __half* p = A + (size_t)r * KBIG;
    p[k] = hi; p[IN_F + k] = lo; p[2 * IN_F + k] = hi;
}

__global__ void split_W_h(const float* __restrict__ W, __half* __restrict__ Bb) {
    __shared__ float t[32][33];
    int nb = blockIdx.x * 32, kb = blockIdx.y * 32;
    int tx = threadIdx.x, ty0 = threadIdx.y;
    #pragma unroll
    for (int i = 0; i < 32; i += 8) {
        int ty = ty0 + i;
        t[ty][tx] = W[(size_t)(kb + ty) * RFF + nb + tx];
    }
    __syncthreads();
    #pragma unroll
    for (int i = 0; i < 32; i += 8) {
        int ty = ty0 + i;
        int n = nb + ty, k = kb + tx;
        float x = t[tx][ty];
        __half hi = __float2half(x);
        __half lo = __float2half(x - __half2float(hi));
        __half* p = Bb + (size_t)n * KBIG;
        p[k] = hi; p[IN_F + k] = hi; p[2 * IN_F + k] = lo;
    }
}

__global__ void cvt_covh(const float* __restrict__ c, __half* __restrict__ o) {
    int idx = (blockIdx.x * blockDim.x + threadIdx.x) * 4;
    if (idx >= RFF * RFF) return;
    float4 v = *(const float4*)(c + idx);
    __half2 a, b;
    a.x = __float2half(v.x); a.y = __float2half(v.y);
    b.x = __float2half(v.z); b.y = __float2half(v.w);
    *(__half2*)(o + idx) = a;
    *(__half2*)(o + idx + 2) = b;
}

__global__ void cvt_lwh(const float* __restrict__ lw, __half* __restrict__ o) {
    int idx = blockIdx.x * blockDim.x + threadIdx.x;
    if (idx >= OUT_P * RFF) return;
    int n = idx >> 11;
    o[idx] = (n < OUT_F) ? __float2half(lw[idx]) : __float2half(0.0f);
}

// ---------------- fp16 persistent GEMM (all three) ----------------
// MODE 0: Phi = fp16(cos(acc+bias)/32); writes Phi(fp32) + Phih + Phih2
//         A=g_Abh [M,KBIG], B=g_Bbh [N,KBIG]
// MODE 1: diag partial = rowsum(acc*Phi); triangular K; A in {Phih2, Phih}; B=covh
// MODE 2: out = (acc+lb)*rsqrt(1+25*diag); A=Phih, B=lwh (padded)
template <int MODE>
__global__ void __launch_bounds__(NTH, 2)
gp_h(const __half* __restrict__ Ag, const __half* __restrict__ Ag2,
     const __half* __restrict__ Bg,
     const float* __restrict__ bias, float* __restrict__ outp,
     __half* __restrict__ outph, __half* __restrict__ outph2,
     const float* __restrict__ phi, float* __restrict__ diagp,
     int* __restrict__ ctr, int nTiles, int K, int nIterFix)
{
    extern __shared__ float dyn[];
    __shared__ int s_tile;
    const int tid = threadIdx.x;
    const int wid = tid >> 5, lane = tid & 31;
    const int g = lane >> 2, t = lane & 3;
    const int warpM = wid >> 2, warpN = wid & 3;   // 2x4 warp grid, 64x32 warp tiles
    const uint32_t sbase = smem_u32(dyn);

    const uint32_t aOff = (uint32_t)((((warpM * 64 + ((lane >> 3) & 1) * 8 + (lane & 7)) * LDSH)
                                      + ((lane >> 4) & 1) * 8) * 2);
    const uint32_t bOff = (uint32_t)(AB_BYTES
                                      + (((warpN * 32 + ((lane >> 4) & 1) * 8 + (lane & 7)) * LDSH
                                      + ((lane >> 3) & 1) * 8) * 2));

    for (;;) {
        if (tid == 0) s_tile = atomicAdd(ctr, 1);
        __syncthreads();
        const int tile = s_tile;
        if (tile >= nTiles) break;

        int rowTile, colTile, cblk;
        if (MODE == 0)      { cblk = tile & 15; rowTile = (tile >> 4) * BM; }
        else if (MODE == 1) { cblk = 15 - (tile >> 6); rowTile = (tile & 63) * BM; }
        else                { cblk = tile & 7;  rowTile = (tile >> 3) * BM; }
        colTile = cblk * BN;
        const int nIter = (MODE == 1) ? ((colTile + BN) / BKB) : nIterFix;

        float acc[4][4][4];
        #pragma unroll
        for (int mt = 0; mt < 4; mt++)
            #pragma unroll
            for (int nt = 0; nt < 4; nt++)
                #pragma unroll
                for (int r = 0; r < 4; r++) acc[mt][nt][r] = 0.0f;

        #define ISSUEH(it, s) do {                                                 \
            const int _k0 = (it) * BKB;                                            \
            const __half* _as = (MODE == 1 && _k0 < colTile) ? Ag2 : Ag;           \
            _Pragma("unroll")                                                      \
            for (int j = 0; j < 4; j++) {                                          \
                int f = tid + NTH * j;                                             \
                int r = f >> 3, q = f & 7;                                         \
                uint32_t d = sbase + (uint32_t)(s) * STAGE_BYTES_B + (uint32_t)((r * LDSH + q * 8) * 2); \
                cp16(d, _as + (size_t)(rowTile + r) * K + _k0 + q * 8);            \
            }                                                                      \
            _Pragma("unroll")                                                      \
            for (int j = 0; j < 4; j++) {                                          \
                int f = tid + NTH * j;                                             \
                int r = f >> 3, q = f & 7;                                         \
                uint32_t d = sbase + (uint32_t)(s) * STAGE_BYTES_B + (uint32_t)(AB_BYTES + (r * LDSH + q * 8) * 2); \
                cp16(d, Bg + (size_t)(colTile + r) * K + _k0 + q * 8);             \
            }                                                                      \
            cp_commit();                                                           \
        } while (0)

        ISSUEH(0, 0);
        ISSUEH(1, 1);

        int s = 0;
        for (int it = 0; it < nIter; ++it) {
            if (it + 1 < nIter) cp_wait<1>(); else cp_wait<0>();
            __syncthreads();
            if (it + 2 < nIter) ISSUEH(it + 2, (s + 2) % NSTAGE);

            const uint32_t aB = sbase + (uint32_t)s * STAGE_BYTES_B + aOff;
            const uint32_t bB = sbase + (uint32_t)s * STAGE_BYTES_B + bOff;
            #pragma unroll
            for (int kk = 0; kk < 4; kk++) {        // 4 x k16 = BKB
                uint32_t af[4][4], bf[4][2];
                #pragma unroll
                for (int mt = 0; mt < 4; mt++)
                    ldsm_x4(af[mt], aB + (uint32_t)((mt * 16 * LDSH + kk * 16) * 2));
                #pragma unroll
                for (int np = 0; np < 2; np++) {
                    uint32_t r4[4];
                    ldsm_x4(r4, bB + (uint32_t)((np * 16 * LDSH + kk * 16) * 2));
                    bf[2 * np][0] = r4[0]; bf[2 * np][1] = r4[1];
                    bf[2 * np + 1][0] = r4[2]; bf[2 * np + 1][1] = r4[3];
                }
                #pragma unroll
                for (int mt = 0; mt < 4; mt++)
                    #pragma unroll
                    for (int nt = 0; nt < 4; nt++)
                        mma_f16(acc[mt][nt], af[mt], bf[nt]);
            }
            s = (s + 1 == NSTAGE) ? 0 : s + 1;
        }
        __syncthreads();

        // ---------------- epilogues ----------------
        if (MODE == 0) {
            #pragma unroll
            for (int mt = 0; mt < 4; mt++)
                #pragma unroll
                for (int h = 0; h < 2; h++) {
                    const int R = rowTile + warpM * 64 + mt * 16 + g + h * 8;
                    float* op = outp + (size_t)R * RFF;
                    __half* oph  = outph  + (size_t)R * RFF;
                    __half* oph2 = outph2 + (size_t)R * RFF;
                    #pragma unroll
                    for (int nt = 0; nt < 4; nt++) {
                        const int C = colTile + warpN * 32 + nt * 8 + 2 * t;
                        float2 bb = *(const float2*)(bias + C);
                        __half2 hh, hh2;
                        hh.x = __float2half(cosf(acc[mt][nt][h * 2 + 0] + bb.x) * INV_RFF_SCALAR);
                        hh.y = __float2half(cosf(acc[mt][nt][h * 2 + 1] + bb.y) * INV_RFF_SCALAR);
                        float2 o;
                        o.x = __half2float(hh.x);
                        o.y = __half2float(hh.y);
                        hh2.x = __float2half(2.0f * o.x);
                        hh2.y = __float2half(2.0f * o.y);
                        *(float2*)(op + C) = o;
                        *(__half2*)(oph + C) = hh;
                        *(__half2*)(oph2 + C) = hh2;
                    }
                }
        } else if (MODE == 1) {
            float* red = dyn;  // [128][4]
            #pragma unroll
            for (int mt = 0; mt < 4; mt++)
                #pragma unroll
                for (int h = 0; h < 2; h++) {
                    const int lr = warpM * 64 + mt * 16 + g + h * 8;
                    const float* pr = phi + (size_t)(rowTile + lr) * RFF;
                    float sum = 0.0f;
                    #pragma unroll
                    for (int nt = 0; nt < 4; nt++) {
                        const int C = colTile + warpN * 32 + nt * 8 + 2 * t;
                        float2 p = *(const float2*)(pr + C);
                        sum = fmaf(acc[mt][nt][h * 2 + 0], p.x, sum);
                        sum = fmaf(acc[mt][nt][h * 2 + 1], p.y, sum);
                    }
                    sum += __shfl_xor_sync(0xffffffffu, sum, 1);
                    sum += __shfl_xor_sync(0xffffffffu, sum, 2);
                    if (t == 0) red[lr * 4 + warpN] = sum;
                }
            __syncthreads();
            if (tid < 128) {
                float sum = red[tid * 4 + 0] + red[tid * 4 + 1] + red[tid * 4 + 2] + red[tid * 4 + 3];
                diagp[(size_t)cblk * NROWS + rowTile + tid] = sum;
            }
            __syncthreads();
        } else {
            float* scale = dyn;  // [128]
            if (tid < 128) {
                float dg = 0.0f;
                #pragma unroll
                for (int p = 0; p < 16; p++) dg += diagp[(size_t)p * NROWS + rowTile + tid];
                scale[tid] = rsqrtf(1.0f + MFF * dg);
            }
            __syncthreads();
            #pragma unroll
            for (int mt = 0; mt < 4; mt++)
                #pragma unroll
                for (int h = 0; h < 2; h++) {
                    const int lr = warpM * 64 + mt * 16 + g + h * 8;
                    const int R = rowTile + lr;
                    const float sc = scale[lr];
                    float* op = outp + (size_t)R * OUT_F;
                    #pragma unroll
                    for (int nt = 0; nt < 4; nt++) {
                        const int C = colTile + warpN * 32 + nt * 8 + 2 * t;
                        if (C < OUT_F) {
                            float2 bb = *(const float2*)(bias + C);
                            float2 o;
                            o.x = (acc[mt][nt][h * 2 + 0] + bb.x) * sc;
                            o.y = (acc[mt][nt][h * 2 + 1] + bb.y) * sc;
                            *(float2*)(op + C) = o;
                        }
                    }
                }
            __syncthreads();
        }
        #undef ISSUEH
    }
}

// ---------------- host ----------------
extern "C" void kernel_launch(void* const* d_in, const int* in_sizes, int n_in,
                              void* d_out, int out_size)
{
    const float* D   = (const float*)d_in[0];
    const float* W   = (const float*)d_in[1];
    const float* b   = (const float*)d_in[2];
    const float* lw  = (const float*)d_in[3];
    const float* lb  = (const float*)d_in[4];
    const float* cov = (const float*)d_in[5];
    float* out = (float*)d_out;

    float *Phi, *diagp;
    __half *Phih, *Phih2, *covh, *lwh, *Abh, *Bbh;
    int* ctr;
    cudaGetSymbolAddress((void**)&Phi,   g_Phi);
    cudaGetSymbolAddress((void**)&Phih,  g_Phih);
    cudaGetSymbolAddress((void**)&Phih2, g_Phih2);
    cudaGetSymbolAddress((void**)&covh,  g_covh);
    cudaGetSymbolAddress((void**)&lwh,   g_lwh);
    cudaGetSymbolAddress((void**)&Abh,   g_Abh);
    cudaGetSymbolAddress((void**)&Bbh,   g_Bbh);
    cudaGetSymbolAddress((void**)&diagp, g_diag_part);
    cudaGetSymbolAddress((void**)&ctr,   g_ctr);

    const int smem = NSTAGE * STAGE_BYTES_B;  // 110592 bytes
    cudaFuncSetAttribute(gp_h<0>, cudaFuncAttributeMaxDynamicSharedMemorySize, smem);
    cudaFuncSetAttribute(gp_h<1>, cudaFuncAttributeMaxDynamicSharedMemorySize, smem);
    cudaFuncSetAttribute(gp_h<2>, cudaFuncAttributeMaxDynamicSharedMemorySize, smem);

    cudaMemsetAsync(ctr, 0, 4 * sizeof(int));

    split_D_h<<<(NROWS * IN_F + 255) / 256, 256>>>(D, Abh);
    split_W_h<<<dim3(RFF / 32, IN_F / 32), dim3(32, 8)>>>(W, Bbh);
    cvt_covh<<<(RFF * RFF / 4 + 255) / 256, 256>>>(cov, covh);
    cvt_lwh<<<(OUT_P * RFF + 255) / 256, 256>>>(lw, lwh);

    // GEMM1: fp16 3-product split, K=1536, 1024 tiles; writes Phi + Phih + Phih2
    gp_h<0><<<GRID_P, NTH, smem>>>(
        Abh, nullptr, Bbh, b, Phi, Phih, Phih2, nullptr, nullptr,
        ctr + 0, 1024, KBIG, KBIG / BKB);
    // GEMM2: fp16 triangular diag partials, 1024 tiles LPT
    gp_h<1><<<GRID_P, NTH, smem>>>(
        Phih, Phih2, covh, nullptr, nullptr, nullptr, nullptr, Phi, diagp,
        ctr + 1, 1024, RFF, 0);
    // GEMM3: fp16 single-pass, K=2048, A=Phih (exact), B=lwh padded, 512 tiles
    gp_h<2><<<GRID_P, NTH, smem>>>(
        Phih, nullptr, lwh, lb, out, nullptr, nullptr, nullptr, diagp,
        ctr + 2, 512, RFF, RFF / BKB);
}

// round 13
// speedup vs baseline: 2.1675x; 1.0175x over previous
#include <cuda_runtime.h>
#include <cuda_fp16.h>
#include <math.h>
#include <stdint.h>

// ---------------- problem constants ----------------
#define NROWS 8192
#define IN_F  512
#define RFF   2048
#define OUT_F 1000
#define OUT_P 1024
#define KBIG  (3*IN_F)                 // 1536: [Dhi|Dlo|Dhi] x [Whi|Whi|Wlo] (fp16)
#define INV_RFF_SCALAR (1.0f/32.0f)
#define MFF   25.0f

// ---------------- fp16 tiling ----------------
#define BM 128
#define BN 128
#define BKB 64
#define LDSH 72                        // halves per smem row (144 B)
#define AB_BYTES (128*LDSH*2)          // 18432
#define STAGE_BYTES_B (2*AB_BYTES)     // 36864
#define NSTAGE 3
#define NTH 256
#define GRID_P 296

// tile queue: [0,1024) GEMM1, [1024,2048) GEMM2, [2048,2560) GEMM3
#define T_G2 1024
#define T_G3 2048
#define T_END 2560

// ---------------- device scratch ----------------
__device__ float  g_Phi[NROWS*RFF];
__device__ __half g_Phih [NROWS*RFF];
__device__ __half g_Phih2[NROWS*RFF];
__device__ __half g_covh [RFF*RFF];
__device__ __half g_lwh  [OUT_P*RFF];
__device__ __half g_Abh[NROWS*KBIG];
__device__ __half g_Bbh[RFF*KBIG];
__device__ float  g_diag_part[16*NROWS];
__device__ int    g_sync[2 + 64 + 64];  // [0]=tile ctr, [2..65]=done1, [66..129]=done2

// ---------------- helpers ----------------
__device__ __forceinline__ uint32_t smem_u32(const void* p) {
    uint32_t r;
    asm("{ .reg .u64 t; cvta.to.shared.u64 t, %1; cvt.u32.u64 %0, t; }" : "=r"(r) : "l"(p));
    return r;
}
__device__ __forceinline__ void cp16(uint32_t d, const void* s) {
    asm volatile("cp.async.cg.shared.global [%0], [%1], 16;" :: "r"(d), "l"(s));
}
__device__ __forceinline__ void cp_commit() { asm volatile("cp.async.commit_group;"); }
template <int N> __device__ __forceinline__ void cp_wait() {
    asm volatile("cp.async.wait_group %0;" :: "n"(N));
}
__device__ __forceinline__ void ldsm_x4(uint32_t* r, uint32_t a) {
    asm volatile("ldmatrix.sync.aligned.m8n8.x4.shared.b16 {%0,%1,%2,%3}, [%4];"
        : "=r"(r[0]), "=r"(r[1]), "=r"(r[2]), "=r"(r[3]) : "r"(a));
}
__device__ __forceinline__ void mma_f16(float* c, const uint32_t* a, const uint32_t* b) {
    asm volatile(
        "mma.sync.aligned.m16n8k16.row.col.f32.f16.f16.f32 "
        "{%0,%1,%2,%3}, {%4,%5,%6,%7}, {%8,%9}, {%0,%1,%2,%3};"
        : "+f"(c[0]), "+f"(c[1]), "+f"(c[2]), "+f"(c[3])
        : "r"(a[0]), "r"(a[1]), "r"(a[2]), "r"(a[3]), "r"(b[0]), "r"(b[1]));
}

// ---------------- fused prep kernel ----------------
#define PD_BLKS 16384
#define PW_BLKS 1024
#define PC_BLKS 4096
#define PL_BLKS 8192
__global__ void prep_all(const float* __restrict__ D, const float* __restrict__ W,
                         const float* __restrict__ cov, const float* __restrict__ lw,
                         __half* __restrict__ Abh, __half* __restrict__ Bbh,
                         __half* __restrict__ covh, __half* __restrict__ lwh)
{
    const int blk = blockIdx.x;
    const int tid = threadIdx.x;
    if (blk < PD_BLKS) {
        int idx = blk * 256 + tid;
        int r = idx >> 9, k = idx & (IN_F - 1);
        float x = D[idx];
        __half hi = __float2half(x);
        __half lo = __float2half(x - __half2float(hi));
        __half* p = Abh + (size_t)r * KBIG;
        p[k] = hi; p[IN_F + k] = lo; p[2 * IN_F + k] = hi;
    } else if (blk < PD_BLKS + PW_BLKS) {
        __shared__ float t[32][33];
        int wb = blk - PD_BLKS;
        int nb = (wb & 63) * 32, kb = (wb >> 6) * 32;
        int tx = tid & 31, ty0 = tid >> 5;
        #pragma unroll
        for (int i = 0; i < 32; i += 8) {
            int ty = ty0 + i;
            t[ty][tx] = W[(size_t)(kb + ty) * RFF + nb + tx];
        }
        __syncthreads();
        #pragma unroll
        for (int i = 0; i < 32; i += 8) {
            int ty = ty0 + i;
            int n = nb + ty, k = kb + tx;
            float x = t[tx][ty];
            __half hi = __float2half(x);
            __half lo = __float2half(x - __half2float(hi));
            __half* p = Bbh + (size_t)n * KBIG;
            p[k] = hi; p[IN_F + k] = hi; p[2 * IN_F + k] = lo;
        }
    } else if (blk < PD_BLKS + PW_BLKS + PC_BLKS) {
        int idx = ((blk - PD_BLKS - PW_BLKS) * 256 + tid) * 4;
        float4 v = *(const float4*)(cov + idx);
        __half2 a, b;
        a.x = __float2half(v.x); a.y = __float2half(v.y);
        b.x = __float2half(v.z); b.y = __float2half(v.w);
        *(__half2*)(covh + idx) = a;
        *(__half2*)(covh + idx + 2) = b;
    } else {
        int idx = (blk - PD_BLKS - PW_BLKS - PC_BLKS) * 256 + tid;
        int n = idx >> 11;
        lwh[idx] = (n < OUT_F) ? __float2half(lw[idx]) : __float2half(0.0f);
    }
}

// ---------------- fused persistent fp16 GEMM (all three phases) ----------------
__global__ void __launch_bounds__(NTH, 2)
gp_fused(const __half* __restrict__ Abh, const __half* __restrict__ Bbh,
         const __half* __restrict__ Phih, const __half* __restrict__ Phih2,
         const __half* __restrict__ covh, const __half* __restrict__ lwh,
         float* __restrict__ Phi, __half* __restrict__ PhihW, __half* __restrict__ Phih2W,
         float* __restrict__ diagp,
         const float* __restrict__ biasb, const float* __restrict__ lb,
         float* __restrict__ outp, int* __restrict__ sync)
{
    extern __shared__ float dyn[];
    __shared__ int s_tile;
    const int tid = threadIdx.x;
    const int wid = tid >> 5, lane = tid & 31;
    const int g = lane >> 2, t = lane & 3;
    const int warpM = wid >> 2, warpN = wid & 3;   // 2x4 warp grid, 64x32 warp tiles
    const uint32_t sbase = smem_u32(dyn);
    int* done1 = sync + 2;
    int* done2 = sync + 66;

    const uint32_t aOff = (uint32_t)((((warpM * 64 + ((lane >> 3) & 1) * 8 + (lane & 7)) * LDSH)
                                      + ((lane >> 4) & 1) * 8) * 2);
    const uint32_t bOff = (uint32_t)(AB_BYTES
                                      + (((warpN * 32 + ((lane >> 4) & 1) * 8 + (lane & 7)) * LDSH
                                      + ((lane >> 3) & 1) * 8) * 2));

    for (;;) {
        if (tid == 0) s_tile = atomicAdd(sync, 1);
        __syncthreads();
        const int tile = s_tile;
        if (tile >= T_END) break;

        int mode, rowb, cblk;
        if (tile < T_G2)      { mode = 0; rowb = tile >> 4; cblk = tile & 15; }
        else if (tile < T_G3) { mode = 1; rowb = (tile - T_G2) >> 4; cblk = (tile - T_G2) & 15; }
        else                  { mode = 2; rowb = (tile - T_G3) >> 3; cblk = (tile - T_G3) & 7; }
        const int rowTile = rowb * BM, colTile = cblk * BN;

        const __half *Aptr, *Bptr;
        int K, nIter;
        if (mode == 0)      { Aptr = Abh;  Bptr = Bbh;  K = KBIG; nIter = KBIG / BKB; }
        else if (mode == 1) { Aptr = Phih; Bptr = covh; K = RFF;  nIter = (colTile + BN) / BKB; }
        else                { Aptr = Phih; Bptr = lwh;  K = RFF;  nIter = RFF / BKB; }

        // dependency spin (release/acquire via threadfence + atomics; consumers L2-coherent)
        if (mode == 1) {
            if (tid == 0) { while (atomicAdd(done1 + rowb, 0) < 16) __nanosleep(64); __threadfence(); }
            __syncthreads();
        } else if (mode == 2) {
            if (tid == 0) { while (atomicAdd(done2 + rowb, 0) < 16) __nanosleep(64); __threadfence(); }
            __syncthreads();
        }

        float acc[4][4][4];
        #pragma unroll
        for (int mt = 0; mt < 4; mt++)
            #pragma unroll
            for (int nt = 0; nt < 4; nt++)
                #pragma unroll
                for (int r = 0; r < 4; r++) acc[mt][nt][r] = 0.0f;

        #define ISSUEH(it, s) do {                                                 \
            const int _k0 = (it) * BKB;                                            \
            const __half* _as = (mode == 1 && _k0 < colTile) ? Phih2 : Aptr;       \
            _Pragma("unroll")                                                      \
            for (int j = 0; j < 4; j++) {                                          \
                int f = tid + NTH * j;                                             \
                int r = f >> 3, q = f & 7;                                         \
                uint32_t d = sbase + (uint32_t)(s) * STAGE_BYTES_B + (uint32_t)((r * LDSH + q * 8) * 2); \
                cp16(d, _as + (size_t)(rowTile + r) * K + _k0 + q * 8);            \
            }                                                                      \
            _Pragma("unroll")                                                      \
            for (int j = 0; j < 4; j++) {                                          \
                int f = tid + NTH * j;                                             \
                int r = f >> 3, q = f & 7;                                         \
                uint32_t d = sbase + (uint32_t)(s) * STAGE_BYTES_B + (uint32_t)(AB_BYTES + (r * LDSH + q * 8) * 2); \
                cp16(d, Bptr + (size_t)(colTile + r) * K + _k0 + q * 8);           \
            }                                                                      \
            cp_commit();                                                           \
        } while (0)

        ISSUEH(0, 0);
        ISSUEH(1, 1);

        int s = 0;
        for (int it = 0; it < nIter; ++it) {
            if (it + 1 < nIter) cp_wait<1>(); else cp_wait<0>();
            __syncthreads();
            if (it + 2 < nIter) ISSUEH(it + 2, (s + 2) % NSTAGE);

            const uint32_t aB = sbase + (uint32_t)s * STAGE_BYTES_B + aOff;
            const uint32_t bB = sbase + (uint32_t)s * STAGE_BYTES_B + bOff;
            #pragma unroll
            for (int kk = 0; kk < 4; kk++) {
                uint32_t af[4][4], bf[4][2];
                #pragma unroll
                for (int mt = 0; mt < 4; mt++)
                    ldsm_x4(af[mt], aB + (uint32_t)((mt * 16 * LDSH + kk * 16) * 2));
                #pragma unroll
                for (int np = 0; np < 2; np++) {
                    uint32_t r4[4];
                    ldsm_x4(r4, bB + (uint32_t)((np * 16 * LDSH + kk * 16) * 2));
                    bf[2 * np][0] = r4[0]; bf[2 * np][1] = r4[1];
                    bf[2 * np + 1][0] = r4[2]; bf[2 * np + 1][1] = r4[3];
                }
                #pragma unroll
                for (int mt = 0; mt < 4; mt++)
                    #pragma unroll
                    for (int nt = 0; nt < 4; nt++)
                        mma_f16(acc[mt][nt], af[mt], bf[nt]);
            }
            s = (s + 1 == NSTAGE) ? 0 : s + 1;
        }
        __syncthreads();

        // ---------------- epilogues ----------------
        if (mode == 0) {
            #pragma unroll
            for (int mt = 0; mt < 4; mt++)
                #pragma unroll
                for (int h = 0; h < 2; h++) {
                    const int R = rowTile + warpM * 64 + mt * 16 + g + h * 8;
                    float* op = Phi + (size_t)R * RFF;
                    __half* oph  = PhihW  + (size_t)R * RFF;
                    __half* oph2 = Phih2W + (size_t)R * RFF;
                    #pragma unroll
                    for (int nt = 0; nt < 4; nt++) {
                        const int C = colTile + warpN * 32 + nt * 8 + 2 * t;
                        float2 bb = *(const float2*)(biasb + C);
                        __half2 hh, hh2;
                        hh.x = __float2half(cosf(acc[mt][nt][h * 2 + 0] + bb.x) * INV_RFF_SCALAR);
                        hh.y = __float2half(cosf(acc[mt][nt][h * 2 + 1] + bb.y) * INV_RFF_SCALAR);
                        float2 o;
                        o.x = __half2float(hh.x);
                        o.y = __half2float(hh.y);
                        hh2.x = __float2half(2.0f * o.x);
                        hh2.y = __float2half(2.0f * o.y);
                        *(float2*)(op + C) = o;
                        *(__half2*)(oph + C) = hh;
                        *(__half2*)(oph2 + C) = hh2;
                    }
                }
            __threadfence();
            __syncthreads();
            if (tid == 0) atomicAdd(done1 + rowb, 1);
        } else if (mode == 1) {
            float* red = dyn;  // [128][4]
            #pragma unroll
            for (int mt = 0; mt < 4; mt++)
                #pragma unroll
                for (int h = 0; h < 2; h++) {
                    const int lr = warpM * 64 + mt * 16 + g + h * 8;
                    const float* pr = Phi + (size_t)(rowTile + lr) * RFF;
                    float sum = 0.0f;
                    #pragma unroll
                    for (int nt = 0; nt < 4; nt++) {
                        const int C = colTile + warpN * 32 + nt * 8 + 2 * t;
                        float2 p = __ldcg((const float2*)(pr + C));
                        sum = fmaf(acc[mt][nt][h * 2 + 0], p.x, sum);
                        sum = fmaf(acc[mt][nt][h * 2 + 1], p.y, sum);
                    }
                    sum += __shfl_xor_sync(0xffffffffu, sum, 1);
                    sum += __shfl_xor_sync(0xffffffffu, sum, 2);
                    if (t == 0) red[lr * 4 + warpN] = sum;
                }
            __syncthreads();
            if (tid < 128) {
                float sum = red[tid * 4 + 0] + red[tid * 4 + 1] + red[tid * 4 + 2] + red[tid * 4 + 3];
                diagp[(size_t)cblk * NROWS + rowTile + tid] = sum;
            }
            __threadfence();
            __syncthreads();
            if (tid == 0) atomicAdd(done2 + rowb, 1);
        } else {
            float* scale = dyn;  // [128]
            if (tid < 128) {
                float dg = 0.0f;
                #pragma unroll
                for (int p = 0; p < 16; p++) dg += __ldcg(diagp + (size_t)p * NROWS + rowTile + tid);
                scale[tid] = rsqrtf(1.0f + MFF * dg);
            }
            __syncthreads();
            #pragma unroll
            for (int mt = 0; mt < 4; mt++)
                #pragma unroll
                for (int h = 0; h < 2; h++) {
                    const int lr = warpM * 64 + mt * 16 + g + h * 8;
                    const int R = rowTile + lr;
                    const float sc = scale[lr];
                    float* op = outp + (size_t)R * OUT_F;
                    #pragma unroll
                    for (int nt = 0; nt < 4; nt++) {
                        const int C = colTile + warpN * 32 + nt * 8 + 2 * t;
                        if (C < OUT_F) {
                            float2 bb = *(const float2*)(lb + C);
                            float2 o;
                            o.x = (acc[mt][nt][h * 2 + 0] + bb.x) * sc;
                            o.y = (acc[mt][nt][h * 2 + 1] + bb.y) * sc;
                            *(float2*)(op + C) = o;
                        }
                    }
                }
            __syncthreads();
        }
        #undef ISSUEH
    }
}

// ---------------- host ----------------
extern "C" void kernel_launch(void* const* d_in, const int* in_sizes, int n_in,
                              void* d_out, int out_size)
{
    const float* D   = (const float*)d_in[0];
    const float* W   = (const float*)d_in[1];
    const float* b   = (const float*)d_in[2];
    const float* lw  = (const float*)d_in[3];
    const float* lb  = (const float*)d_in[4];
    const float* cov = (const float*)d_in[5];
    float* out = (float*)d_out;

    float *Phi, *diagp;
    __half *Phih, *Phih2, *covh, *lwh, *Abh, *Bbh;
    int* sync;
    cudaGetSymbolAddress((void**)&Phi,   g_Phi);
    cudaGetSymbolAddress((void**)&Phih,  g_Phih);
    cudaGetSymbolAddress((void**)&Phih2, g_Phih2);
    cudaGetSymbolAddress((void**)&covh,  g_covh);
    cudaGetSymbolAddress((void**)&lwh,   g_lwh);
    cudaGetSymbolAddress((void**)&Abh,   g_Abh);
    cudaGetSymbolAddress((void**)&Bbh,   g_Bbh);
    cudaGetSymbolAddress((void**)&diagp, g_diag_part);
    cudaGetSymbolAddress((void**)&sync,  g_sync);

    const int smem = NSTAGE * STAGE_BYTES_B;  // 110592 bytes
    cudaFuncSetAttribute(gp_fused, cudaFuncAttributeMaxDynamicSharedMemorySize, smem);

    cudaMemsetAsync(sync, 0, (2 + 64 + 64) * sizeof(int));

    prep_all<<<PD_BLKS + PW_BLKS + PC_BLKS + PL_BLKS, 256>>>(
        D, W, cov, lw, Abh, Bbh, covh, lwh);

    gp_fused<<<GRID_P, NTH, smem>>>(
        Abh, Bbh, Phih, Phih2, covh, lwh,
        Phi, Phih, Phih2, diagp, b, lb, out, sync);
}